// round 16
// baseline (speedup 1.0000x reference)
#include <cuda_runtime.h>
#include <math.h>

#define PTS 64
#define HD  20

typedef unsigned long long u64;

// edgeconv weight blob offsets (floats), per round
#define E_WA 0
#define E_BA 800
#define E_WB 820
#define E_BB 1220
#define E_TOT 1240
// input-MLP blob offsets (floats)
#define I_W0 0
#define I_B0 60
#define I_W1 80
#define I_B1 480
#define I_W2 500
#define I_B2 900
#define I_TOT 920

__device__ __forceinline__ u64 pk2(float a, float b) {
    u64 r; asm("mov.b64 %0, {%1, %2};" : "=l"(r) : "f"(a), "f"(b)); return r;
}
__device__ __forceinline__ void up2(u64 v, float& a, float& b) {
    asm("mov.b64 {%0, %1}, %2;" : "=f"(a), "=f"(b) : "l"(v));
}
__device__ __forceinline__ u64 splat2(float f) { return pk2(f, f); }
__device__ __forceinline__ u64 fma2v(u64 a, u64 b, u64 c) {
    u64 d; asm("fma.rn.f32x2 %0, %1, %2, %3;" : "=l"(d) : "l"(a), "l"(b), "l"(c)); return d;
}
__device__ __forceinline__ u64 add2v(u64 a, u64 b) {
    u64 d; asm("add.rn.f32x2 %0, %1, %2;" : "=l"(d) : "l"(a), "l"(b)); return d;
}
__device__ __forceinline__ float eluf(float v) { return v > 0.f ? v : (__expf(v) - 1.0f); }

// float4 staging: every blob size here is a multiple of 4 floats and every
// src/dst offset is 16B-aligned.
__device__ __forceinline__ void stage4(float* dst, const float* __restrict__ src,
                                       int n4, int tid) {
    const float4* s = reinterpret_cast<const float4*>(src);
    float4* d = reinterpret_cast<float4*>(dst);
    for (int t = tid; t < n4; t += PTS) d[t] = s[t];
}

// 20->20 dense on packed pairs; input/output in h regs (e-loop fully unrolled),
// weights/bias rows 16B-aligned in shared. Applies ELU to output.
__device__ __forceinline__ void dense20p(const float* W, const float* bias, float* h) {
    u64 o[10];
    const ulonglong2* bp = reinterpret_cast<const ulonglong2*>(bias);
#pragma unroll
    for (int q = 0; q < 5; ++q) { ulonglong2 v = bp[q]; o[2 * q] = v.x; o[2 * q + 1] = v.y; }
#pragma unroll
    for (int e = 0; e < HD; ++e) {
        u64 f = splat2(h[e]);
        const ulonglong2* wp = reinterpret_cast<const ulonglong2*>(W + e * HD);
#pragma unroll
        for (int q = 0; q < 5; ++q) {
            ulonglong2 w = wp[q];
            o[2 * q]     = fma2v(f, w.x, o[2 * q]);
            o[2 * q + 1] = fma2v(f, w.y, o[2 * q + 1]);
        }
    }
#pragma unroll
    for (int q = 0; q < 10; ++q) {
        float a, bv; up2(o[q], a, bv);
        h[2 * q] = eluf(a); h[2 * q + 1] = eluf(bv);
    }
}

__global__ __launch_bounds__(PTS, 10)
void net_kernel(const float* __restrict__ x,
                const float* __restrict__ Wi0, const float* __restrict__ bi0,
                const float* __restrict__ Wi1, const float* __restrict__ bi1,
                const float* __restrict__ Wi2, const float* __restrict__ bi2,
                const float* __restrict__ Wa0, const float* __restrict__ ba0,
                const float* __restrict__ Wb0, const float* __restrict__ bb0,
                const float* __restrict__ Wa1, const float* __restrict__ ba1,
                const float* __restrict__ Wb1, const float* __restrict__ bb1,
                const float* __restrict__ Wo0, const float* __restrict__ bo0,
                const float* __restrict__ Wo1, const float* __restrict__ bo1,
                const float* __restrict__ Wo2, const float* __restrict__ bo2,
                float* __restrict__ out) {
    __shared__ __align__(16) float sWi[I_TOT];       // input MLP weights
    __shared__ __align__(16) float sWe[2][E_TOT];    // BOTH edgeconv rounds, staged once
    // sh is time-multiplexed: h (KNN) -> v = Wlow.h (layer2) -> edgeconv output (pool)
    __shared__ __align__(16) float sh[PTS][HD];
    __shared__ __align__(16) float ssq[PTS];
    __shared__ float sval[PTS];
    __shared__ __align__(16) int sc[PTS];
    __shared__ float sg[HD];
    __shared__ float sg2[HD];
    __shared__ float slog[10];
    __shared__ float slse;

    const int tid = threadIdx.x;
    const int b = blockIdx.x;

    // early global loads
    const float x0 = x[(b * PTS + tid) * 3 + 0];
    const float x1 = x[(b * PTS + tid) * 3 + 1];
    const float x2 = x[(b * PTS + tid) * 3 + 2];

    // ---- stage ALL weights once (input MLP + both edgeconv rounds) ----
    stage4(sWi + I_W0, Wi0, 15, tid);
    stage4(sWi + I_B0, bi0, 5, tid);
    stage4(sWi + I_W1, Wi1, 100, tid);
    stage4(sWi + I_B1, bi1, 5, tid);
    stage4(sWi + I_W2, Wi2, 100, tid);
    stage4(sWi + I_B2, bi2, 5, tid);
    stage4(sWe[0] + E_WA, Wa0, 200, tid);
    stage4(sWe[0] + E_BA, ba0, 5, tid);
    stage4(sWe[0] + E_WB, Wb0, 100, tid);
    stage4(sWe[0] + E_BB, bb0, 5, tid);
    stage4(sWe[1] + E_WA, Wa1, 200, tid);
    stage4(sWe[1] + E_BA, ba1, 5, tid);
    stage4(sWe[1] + E_WB, Wb1, 100, tid);
    stage4(sWe[1] + E_BB, bb1, 5, tid);
    sval[tid] = 1.f;
    __syncthreads();

    // ---- input MLP: 3 -> 20 -> 20 -> 20, result in h regs ----
    float h[HD];
#pragma unroll
    for (int d = 0; d < HD; ++d) {
        float v = sWi[I_B0 + d];
        v = fmaf(x0, sWi[I_W0 + 0 * HD + d], v);
        v = fmaf(x1, sWi[I_W0 + 1 * HD + d], v);
        v = fmaf(x2, sWi[I_W0 + 2 * HD + d], v);
        h[d] = eluf(v);
    }
    dense20p(sWi + I_W1, sWi + I_B1, h);
    dense20p(sWi + I_W2, sWi + I_B2, h);

    bool myvalid = true;

    // ---- two EdgeConv + pool rounds ----
#pragma unroll 1
    for (int r = 0; r < 2; ++r) {
        const float* sW = sWe[r];
        __syncthreads();  // previous readers of sh (pool) are done

        // publish h (packed) + ssq (+INF marks invalid)
#pragma unroll
        for (int q = 0; q < 5; ++q)
            reinterpret_cast<float4*>(&sh[tid][0])[q] =
                make_float4(h[4 * q], h[4 * q + 1], h[4 * q + 2], h[4 * q + 3]);
        float sq = 0.f;
#pragma unroll
        for (int d = 0; d < HD; ++d) sq = fmaf(h[d], h[d], sq);
        ssq[tid] = myvalid ? sq : INFINITY;
        __syncthreads();

        // ---- KNN top-4 via two independent parity tournaments + stable merge ----
        // hi2 pre-doubled: power-of-2 scaling is rounding-invariant, so the
        // score is bit-identical to 2.f*dot - sq - ssq[j].
        u64 hi2[10];
#pragma unroll
        for (int q = 0; q < 10; ++q) hi2[q] = pk2(2.f * h[2 * q], 2.f * h[2 * q + 1]);

        float sa0 = -INFINITY, sa1 = -INFINITY, sa2 = -INFINITY, sa3 = -INFINITY;
        float sb0 = -INFINITY, sb1 = -INFINITY, sb2 = -INFINITY, sb3 = -INFINITY;
        int ia0 = 0, ia1 = 2, ia2 = 4, ia3 = 6;
        int ib0 = 1, ib1 = 3, ib2 = 5, ib3 = 7;

#pragma unroll 1
        for (int jb = 0; jb < PTS; jb += 4) {
            const float4 sqq = *reinterpret_cast<const float4*>(&ssq[jb]);
            float sj[4];
            // 4 independent dot products first (max ILP)
#pragma unroll
            for (int k = 0; k < 4; ++k) {
                const int j = jb + k;
                const float ssqj = (k == 0) ? sqq.x : (k == 1) ? sqq.y
                                 : (k == 2) ? sqq.z : sqq.w;
                const ulonglong2* hp = reinterpret_cast<const ulonglong2*>(&sh[j][0]);
                u64 pa = 0ull, pb = 0ull;
#pragma unroll
                for (int q = 0; q < 5; ++q) {
                    ulonglong2 w = hp[q];
                    pa = fma2v(hi2[2 * q], w.x, pa);
                    pb = fma2v(hi2[2 * q + 1], w.y, pb);
                }
                u64 pc = add2v(pa, pb);
                float fe, ff; up2(pc, fe, ff);
                float s = (fe + ff) - sq - ssqj;   // (fe+ff) = 2*dot exactly
                sj[k] = (j == tid) ? -INFINITY : s;
            }
            // two independent insertion chains (even -> A, odd -> B)
            {
                const float s = sj[0]; const int j = jb;
                if (s > sa0)      { sa3 = sa2; ia3 = ia2; sa2 = sa1; ia2 = ia1; sa1 = sa0; ia1 = ia0; sa0 = s; ia0 = j; }
                else if (s > sa1) { sa3 = sa2; ia3 = ia2; sa2 = sa1; ia2 = ia1; sa1 = s; ia1 = j; }
                else if (s > sa2) { sa3 = sa2; ia3 = ia2; sa2 = s; ia2 = j; }
                else if (s > sa3) { sa3 = s; ia3 = j; }
            }
            {
                const float s = sj[1]; const int j = jb + 1;
                if (s > sb0)      { sb3 = sb2; ib3 = ib2; sb2 = sb1; ib2 = ib1; sb1 = sb0; ib1 = ib0; sb0 = s; ib0 = j; }
                else if (s > sb1) { sb3 = sb2; ib3 = ib2; sb2 = sb1; ib2 = ib1; sb1 = s; ib1 = j; }
                else if (s > sb2) { sb3 = sb2; ib3 = ib2; sb2 = s; ib2 = j; }
                else if (s > sb3) { sb3 = s; ib3 = j; }
            }
            {
                const float s = sj[2]; const int j = jb + 2;
                if (s > sa0)      { sa3 = sa2; ia3 = ia2; sa2 = sa1; ia2 = ia1; sa1 = sa0; ia1 = ia0; sa0 = s; ia0 = j; }
                else if (s > sa1) { sa3 = sa2; ia3 = ia2; sa2 = sa1; ia2 = ia1; sa1 = s; ia1 = j; }
                else if (s > sa2) { sa3 = sa2; ia3 = ia2; sa2 = s; ia2 = j; }
                else if (s > sa3) { sa3 = s; ia3 = j; }
            }
            {
                const float s = sj[3]; const int j = jb + 3;
                if (s > sb0)      { sb3 = sb2; ib3 = ib2; sb2 = sb1; ib2 = ib1; sb1 = sb0; ib1 = ib0; sb0 = s; ib0 = j; }
                else if (s > sb1) { sb3 = sb2; ib3 = ib2; sb2 = sb1; ib2 = ib1; sb1 = s; ib1 = j; }
                else if (s > sb2) { sb3 = sb2; ib3 = ib2; sb2 = s; ib2 = j; }
                else if (s > sb3) { sb3 = s; ib3 = j; }
            }
        }
        // stable 4-way merge: on equal scores pick the lower index (global
        // stability, matching the single-chain insertion exactly).
        int i0, i1, i2, i3;
        {
            int im[4];
#pragma unroll
            for (int t = 0; t < 4; ++t) {
                const bool takeA = (sa0 > sb0) || ((sa0 == sb0) && (ia0 < ib0));
                im[t] = takeA ? ia0 : ib0;
                if (takeA) {
                    sa0 = sa1; ia0 = ia1; sa1 = sa2; ia1 = ia2;
                    sa2 = sa3; ia2 = ia3; sa3 = -INFINITY; ia3 = 1 << 30;
                } else {
                    sb0 = sb1; ib0 = ib1; sb1 = sb2; ib1 = ib2;
                    sb2 = sb3; ib2 = ib3; sb3 = -INFINITY; ib3 = 1 << 30;
                }
            }
            i0 = im[0]; i1 = im[1]; i2 = im[2]; i3 = im[3];
        }

        // ---- fused: u = ba + Wtop^T h AND v = Wlow^T h (one splat per e) ----
        u64 uu[10], vv[10];
        {
            const ulonglong2* bp = reinterpret_cast<const ulonglong2*>(sW + E_BA);
#pragma unroll
            for (int q = 0; q < 5; ++q) {
                ulonglong2 t = bp[q];
                uu[2 * q] = t.x; uu[2 * q + 1] = t.y;
                vv[2 * q] = 0ull; vv[2 * q + 1] = 0ull;
            }
#pragma unroll
            for (int e = 0; e < HD; ++e) {
                u64 f = splat2(h[e]);
                const ulonglong2* wt = reinterpret_cast<const ulonglong2*>(sW + E_WA + e * HD);
                const ulonglong2* wl = reinterpret_cast<const ulonglong2*>(sW + E_WA + (HD + e) * HD);
#pragma unroll
                for (int q = 0; q < 5; ++q) {
                    ulonglong2 a = wt[q], c = wl[q];
                    uu[2 * q]     = fma2v(f, a.x, uu[2 * q]);
                    uu[2 * q + 1] = fma2v(f, a.y, uu[2 * q + 1]);
                    vv[2 * q]     = fma2v(f, c.x, vv[2 * q]);
                    vv[2 * q + 1] = fma2v(f, c.y, vv[2 * q + 1]);
                }
            }
        }
        __syncthreads();  // all KNN readers of sh (h) are done; sh can be reused for v

        // ---- sh[tid] = v; uwf = u - v (20 scalars) ----
        float uwf[HD];
        {
            ulonglong2* vp = reinterpret_cast<ulonglong2*>(&sh[tid][0]);
#pragma unroll
            for (int q = 0; q < 5; ++q) {
                ulonglong2 t; t.x = vv[2 * q]; t.y = vv[2 * q + 1];
                vp[q] = t;
            }
#pragma unroll
            for (int q = 0; q < 10; ++q) {
                float ua, ub, va, vb;
                up2(uu[q], ua, ub); up2(vv[q], va, vb);
                uwf[2 * q] = ua - va;
                uwf[2 * q + 1] = ub - vb;
            }
        }
        __syncthreads();  // v of all threads visible in sh

        // ---- EdgeConv: sum_k elu(elu(uwf + v_j) @ Wb + bb) * valid_j ----
        float acc[HD];
#pragma unroll
        for (int d = 0; d < HD; ++d) acc[d] = 0.f;

        auto do_pass = [&](int j0, int j1) {
            const ulonglong2* vp0 = reinterpret_cast<const ulonglong2*>(&sh[j0][0]);
            const ulonglong2* vp1 = reinterpret_cast<const ulonglong2*>(&sh[j1][0]);
            u64 n0[10], n1[10];
            {
                const ulonglong2* bp = reinterpret_cast<const ulonglong2*>(sW + E_BB);
#pragma unroll
                for (int q = 0; q < 5; ++q) {
                    ulonglong2 t = bp[q];
                    n0[2 * q] = t.x; n0[2 * q + 1] = t.y;
                    n1[2 * q] = t.x; n1[2 * q + 1] = t.y;
                }
            }
            // e-loop grouped by quads: one LDS.128 per neighbor per 4 features.
            // FMA accumulation order (e ascending) identical to scalar version.
#pragma unroll 1
            for (int g = 0; g < 5; ++g) {
                ulonglong2 t0 = vp0[g];
                ulonglong2 t1 = vp1[g];
                float a00, a01, a02, a03, a10, a11, a12, a13;
                up2(t0.x, a00, a01); up2(t0.y, a02, a03);
                up2(t1.x, a10, a11); up2(t1.y, a12, a13);
                float q0[4] = {a00, a01, a02, a03};
                float q1[4] = {a10, a11, a12, a13};
#pragma unroll
                for (int k = 0; k < 4; ++k) {
                    const int e = 4 * g + k;
                    const float uwe = uwf[e];
                    u64 f0 = splat2(eluf(uwe + q0[k]));
                    u64 f1 = splat2(eluf(uwe + q1[k]));
                    const ulonglong2* wp =
                        reinterpret_cast<const ulonglong2*>(sW + E_WB + e * HD);
#pragma unroll
                    for (int q = 0; q < 5; ++q) {
                        ulonglong2 w = wp[q];
                        n0[2 * q]     = fma2v(f0, w.x, n0[2 * q]);
                        n0[2 * q + 1] = fma2v(f0, w.y, n0[2 * q + 1]);
                        n1[2 * q]     = fma2v(f1, w.x, n1[2 * q]);
                        n1[2 * q + 1] = fma2v(f1, w.y, n1[2 * q + 1]);
                    }
                }
            }
            // elu + masked accumulate (neighbor order preserved: j0 then j1)
            const float fj0 = sval[j0];
            const float fj1 = sval[j1];
#pragma unroll
            for (int q = 0; q < 10; ++q) {
                float va, vb;
                up2(n0[q], va, vb);
                acc[2 * q]     = fmaf(eluf(va), fj0, acc[2 * q]);
                acc[2 * q + 1] = fmaf(eluf(vb), fj0, acc[2 * q + 1]);
                up2(n1[q], va, vb);
                acc[2 * q]     = fmaf(eluf(va), fj1, acc[2 * q]);
                acc[2 * q + 1] = fmaf(eluf(vb), fj1, acc[2 * q + 1]);
            }
        };
        do_pass(i0, i1);
        do_pass(i2, i3);

        const float mv = myvalid ? 1.f : 0.f;
        __syncthreads();   // everyone done reading sh (v) in do_pass
        // reuse sh for edgeconv output
#pragma unroll
        for (int q = 0; q < 5; ++q)
            reinterpret_cast<float4*>(&sh[tid][0])[q] =
                make_float4(acc[4 * q] * mv, acc[4 * q + 1] * mv,
                            acc[4 * q + 2] * mv, acc[4 * q + 3] * mv);
        sc[tid] = myvalid ? min(tid, i0) : PTS;
        __syncthreads();

        // ---- pool: thread tid owns cluster slot tid (sc loaded as int4) ----
        float pm[HD];
#pragma unroll
        for (int d = 0; d < HD; ++d) pm[d] = -INFINITY;
        int pcnt = 0;
#pragma unroll 1
        for (int jb = 0; jb < PTS; jb += 4) {
            const int4 cc = *reinterpret_cast<const int4*>(&sc[jb]);
#pragma unroll
            for (int k = 0; k < 4; ++k) {
                const int cj = (k == 0) ? cc.x : (k == 1) ? cc.y
                             : (k == 2) ? cc.z : cc.w;
                if (cj == tid) {
                    ++pcnt;
                    const int j = jb + k;
#pragma unroll
                    for (int q = 0; q < 5; ++q) {
                        float4 v = *reinterpret_cast<const float4*>(&sh[j][4 * q]);
                        pm[4 * q + 0] = fmaxf(pm[4 * q + 0], v.x);
                        pm[4 * q + 1] = fmaxf(pm[4 * q + 1], v.y);
                        pm[4 * q + 2] = fmaxf(pm[4 * q + 2], v.z);
                        pm[4 * q + 3] = fmaxf(pm[4 * q + 3], v.w);
                    }
                }
            }
        }
        myvalid = (pcnt > 0);
        sval[tid] = myvalid ? 1.f : 0.f;
#pragma unroll
        for (int d = 0; d < HD; ++d) h[d] = myvalid ? pm[d] : 0.f;
    }

    // ---- global max over valid points ----
    __syncthreads();   // pool readers of sh are done
#pragma unroll
    for (int d = 0; d < HD; ++d) sh[tid][d] = myvalid ? h[d] : -INFINITY;
    __syncthreads();
    if (tid < HD) {
        float g = -INFINITY;
#pragma unroll 1
        for (int j = 0; j < PTS; ++j) g = fmaxf(g, sh[j][tid]);
        sg[tid] = g;
    }
    __syncthreads();

    // ---- output MLP (weights straight from L2) ----
    if (tid < HD) {
        float a = bo0[tid];
#pragma unroll 1
        for (int e = 0; e < HD; ++e) a = fmaf(sg[e], Wo0[e * HD + tid], a);
        sg2[tid] = eluf(a);
    }
    __syncthreads();
    if (tid < HD) {
        float a = bo1[tid];
#pragma unroll 1
        for (int e = 0; e < HD; ++e) a = fmaf(sg2[e], Wo1[e * HD + tid], a);
        sg[tid] = eluf(a);
    }
    __syncthreads();
    if (tid < 10) {
        float a = bo2[tid];
#pragma unroll 1
        for (int e = 0; e < HD; ++e) a = fmaf(sg[e], Wo2[e * 10 + tid], a);
        slog[tid] = a;
    }
    __syncthreads();
    if (tid == 0) {
        float mx = slog[0];
#pragma unroll
        for (int i = 1; i < 10; ++i) mx = fmaxf(mx, slog[i]);
        float ssum = 0.f;
#pragma unroll
        for (int i = 0; i < 10; ++i) ssum += expf(slog[i] - mx);
        slse = mx + logf(ssum);
    }
    __syncthreads();
    if (tid < 10) out[b * 10 + tid] = slog[tid] - slse;
}

extern "C" void kernel_launch(void* const* d_in, const int* in_sizes, int n_in,
                              void* d_out, int out_size) {
    const float* x = (const float*)d_in[0];
    const int B = in_sizes[0] / (PTS * 3);
    net_kernel<<<B, PTS>>>(
        x,
        (const float*)d_in[1],  (const float*)d_in[2],
        (const float*)d_in[3],  (const float*)d_in[4],
        (const float*)d_in[5],  (const float*)d_in[6],
        (const float*)d_in[7],  (const float*)d_in[8],
        (const float*)d_in[9],  (const float*)d_in[10],
        (const float*)d_in[11], (const float*)d_in[12],
        (const float*)d_in[13], (const float*)d_in[14],
        (const float*)d_in[15], (const float*)d_in[16],
        (const float*)d_in[17], (const float*)d_in[18],
        (const float*)d_in[19], (const float*)d_in[20],
        (float*)d_out);
}

// round 17
// speedup vs baseline: 1.0955x; 1.0955x over previous
#include <cuda_runtime.h>
#include <math.h>

#define PTS 64
#define HD  20

typedef unsigned long long u64;

// per-round edgeconv weight blob (floats)
#define E_WA 0
#define E_BA 800
#define E_WB 820
#define E_BB 1220
#define E_TOT 1240
// input-MLP blob (floats), staged into same sW
#define I_W0 0
#define I_B0 60
#define I_W1 80
#define I_B1 480
#define I_W2 500
#define I_B2 900

__device__ __forceinline__ u64 pk2(float a, float b) {
    u64 r; asm("mov.b64 %0, {%1, %2};" : "=l"(r) : "f"(a), "f"(b)); return r;
}
__device__ __forceinline__ void up2(u64 v, float& a, float& b) {
    asm("mov.b64 {%0, %1}, %2;" : "=f"(a), "=f"(b) : "l"(v));
}
__device__ __forceinline__ u64 splat2(float f) { return pk2(f, f); }
__device__ __forceinline__ u64 fma2v(u64 a, u64 b, u64 c) {
    u64 d; asm("fma.rn.f32x2 %0, %1, %2, %3;" : "=l"(d) : "l"(a), "l"(b), "l"(c)); return d;
}
__device__ __forceinline__ u64 add2v(u64 a, u64 b) {
    u64 d; asm("add.rn.f32x2 %0, %1, %2;" : "=l"(d) : "l"(a), "l"(b)); return d;
}
__device__ __forceinline__ float eluf(float v) { return v > 0.f ? v : (__expf(v) - 1.0f); }

// float4 staging: every blob size here is a multiple of 4 floats and every
// src/dst offset is 16B-aligned.
__device__ __forceinline__ void stage4(float* dst, const float* __restrict__ src,
                                       int n4, int tid) {
    const float4* s = reinterpret_cast<const float4*>(src);
    float4* d = reinterpret_cast<float4*>(dst);
    for (int t = tid; t < n4; t += PTS) d[t] = s[t];
}

// 20->20 dense on packed pairs; input/output in h regs (e-loop fully unrolled),
// weights/bias rows 16B-aligned in shared. Applies ELU to output.
__device__ __forceinline__ void dense20p(const float* W, const float* bias, float* h) {
    u64 o[10];
    const ulonglong2* bp = reinterpret_cast<const ulonglong2*>(bias);
#pragma unroll
    for (int q = 0; q < 5; ++q) { ulonglong2 v = bp[q]; o[2 * q] = v.x; o[2 * q + 1] = v.y; }
#pragma unroll
    for (int e = 0; e < HD; ++e) {
        u64 f = splat2(h[e]);
        const ulonglong2* wp = reinterpret_cast<const ulonglong2*>(W + e * HD);
#pragma unroll
        for (int q = 0; q < 5; ++q) {
            ulonglong2 w = wp[q];
            o[2 * q]     = fma2v(f, w.x, o[2 * q]);
            o[2 * q + 1] = fma2v(f, w.y, o[2 * q + 1]);
        }
    }
#pragma unroll
    for (int q = 0; q < 10; ++q) {
        float a, bv; up2(o[q], a, bv);
        h[2 * q] = eluf(a); h[2 * q + 1] = eluf(bv);
    }
}

__global__ __launch_bounds__(PTS, 10)
void net_kernel(const float* __restrict__ x,
                const float* __restrict__ Wi0, const float* __restrict__ bi0,
                const float* __restrict__ Wi1, const float* __restrict__ bi1,
                const float* __restrict__ Wi2, const float* __restrict__ bi2,
                const float* __restrict__ Wa0, const float* __restrict__ ba0,
                const float* __restrict__ Wb0, const float* __restrict__ bb0,
                const float* __restrict__ Wa1, const float* __restrict__ ba1,
                const float* __restrict__ Wb1, const float* __restrict__ bb1,
                const float* __restrict__ Wo0, const float* __restrict__ bo0,
                const float* __restrict__ Wo1, const float* __restrict__ bo1,
                const float* __restrict__ Wo2, const float* __restrict__ bo2,
                float* __restrict__ out) {
    __shared__ __align__(16) float sW[E_TOT];
    // sh is time-multiplexed: h (KNN) -> v = Wlow.h (layer2) -> edgeconv output (pool)
    __shared__ __align__(16) float sh[PTS][HD];
    __shared__ __align__(16) float ssq[PTS];
    __shared__ float sval[PTS];
    __shared__ __align__(16) int sc[PTS];
    __shared__ float sg[HD];
    __shared__ float sg2[HD];
    __shared__ float slog[10];
    __shared__ float slse;

    const int tid = threadIdx.x;
    const int b = blockIdx.x;

    // early global loads
    const float x0 = x[(b * PTS + tid) * 3 + 0];
    const float x1 = x[(b * PTS + tid) * 3 + 1];
    const float x2 = x[(b * PTS + tid) * 3 + 2];

    // ---- stage input-MLP weights (float4) ----
    stage4(sW + I_W0, Wi0, 15, tid);
    stage4(sW + I_B0, bi0, 5, tid);
    stage4(sW + I_W1, Wi1, 100, tid);
    stage4(sW + I_B1, bi1, 5, tid);
    stage4(sW + I_W2, Wi2, 100, tid);
    stage4(sW + I_B2, bi2, 5, tid);
    sval[tid] = 1.f;
    __syncthreads();

    // ---- input MLP: 3 -> 20 -> 20 -> 20, result in h regs ----
    float h[HD];
#pragma unroll
    for (int d = 0; d < HD; ++d) {
        float v = sW[I_B0 + d];
        v = fmaf(x0, sW[I_W0 + 0 * HD + d], v);
        v = fmaf(x1, sW[I_W0 + 1 * HD + d], v);
        v = fmaf(x2, sW[I_W0 + 2 * HD + d], v);
        h[d] = eluf(v);
    }
    dense20p(sW + I_W1, sW + I_B1, h);
    dense20p(sW + I_W2, sW + I_B2, h);

    bool myvalid = true;

    // ---- two EdgeConv + pool rounds ----
#pragma unroll 1
    for (int r = 0; r < 2; ++r) {
        __syncthreads();  // previous readers of sW / sh are done
        stage4(sW + E_WA, r ? Wa1 : Wa0, 200, tid);
        stage4(sW + E_BA, r ? ba1 : ba0, 5, tid);
        stage4(sW + E_WB, r ? Wb1 : Wb0, 100, tid);
        stage4(sW + E_BB, r ? bb1 : bb0, 5, tid);

        // publish h (packed) + ssq (+INF marks invalid)
#pragma unroll
        for (int q = 0; q < 5; ++q)
            reinterpret_cast<float4*>(&sh[tid][0])[q] =
                make_float4(h[4 * q], h[4 * q + 1], h[4 * q + 2], h[4 * q + 3]);
        float sq = 0.f;
#pragma unroll
        for (int d = 0; d < HD; ++d) sq = fmaf(h[d], h[d], sq);
        ssq[tid] = myvalid ? sq : INFINITY;
        __syncthreads();

        // ---- KNN top-4 via two independent parity tournaments + stable merge ----
        // hi2 pre-doubled: power-of-2 scaling is rounding-invariant, so the
        // score is bit-identical to 2.f*dot - sq - ssq[j].
        u64 hi2[10];
#pragma unroll
        for (int q = 0; q < 10; ++q) hi2[q] = pk2(2.f * h[2 * q], 2.f * h[2 * q + 1]);

        float sa0 = -INFINITY, sa1 = -INFINITY, sa2 = -INFINITY, sa3 = -INFINITY;
        float sb0 = -INFINITY, sb1 = -INFINITY, sb2 = -INFINITY, sb3 = -INFINITY;
        int ia0 = 0, ia1 = 2, ia2 = 4, ia3 = 6;
        int ib0 = 1, ib1 = 3, ib2 = 5, ib3 = 7;

#pragma unroll 1
        for (int jb = 0; jb < PTS; jb += 4) {
            const float4 sqq = *reinterpret_cast<const float4*>(&ssq[jb]);
            float sj[4];
            // 4 independent dot products first (max ILP)
#pragma unroll
            for (int k = 0; k < 4; ++k) {
                const int j = jb + k;
                const float ssqj = (k == 0) ? sqq.x : (k == 1) ? sqq.y
                                 : (k == 2) ? sqq.z : sqq.w;
                const ulonglong2* hp = reinterpret_cast<const ulonglong2*>(&sh[j][0]);
                u64 pa = 0ull, pb = 0ull;
#pragma unroll
                for (int q = 0; q < 5; ++q) {
                    ulonglong2 w = hp[q];
                    pa = fma2v(hi2[2 * q], w.x, pa);
                    pb = fma2v(hi2[2 * q + 1], w.y, pb);
                }
                u64 pc = add2v(pa, pb);
                float fe, ff; up2(pc, fe, ff);
                float s = (fe + ff) - sq - ssqj;   // (fe+ff) = 2*dot exactly
                sj[k] = (j == tid) ? -INFINITY : s;
            }
            // two independent insertion chains (even -> A, odd -> B)
            {
                const float s = sj[0]; const int j = jb;
                if (s > sa0)      { sa3 = sa2; ia3 = ia2; sa2 = sa1; ia2 = ia1; sa1 = sa0; ia1 = ia0; sa0 = s; ia0 = j; }
                else if (s > sa1) { sa3 = sa2; ia3 = ia2; sa2 = sa1; ia2 = ia1; sa1 = s; ia1 = j; }
                else if (s > sa2) { sa3 = sa2; ia3 = ia2; sa2 = s; ia2 = j; }
                else if (s > sa3) { sa3 = s; ia3 = j; }
            }
            {
                const float s = sj[1]; const int j = jb + 1;
                if (s > sb0)      { sb3 = sb2; ib3 = ib2; sb2 = sb1; ib2 = ib1; sb1 = sb0; ib1 = ib0; sb0 = s; ib0 = j; }
                else if (s > sb1) { sb3 = sb2; ib3 = ib2; sb2 = sb1; ib2 = ib1; sb1 = s; ib1 = j; }
                else if (s > sb2) { sb3 = sb2; ib3 = ib2; sb2 = s; ib2 = j; }
                else if (s > sb3) { sb3 = s; ib3 = j; }
            }
            {
                const float s = sj[2]; const int j = jb + 2;
                if (s > sa0)      { sa3 = sa2; ia3 = ia2; sa2 = sa1; ia2 = ia1; sa1 = sa0; ia1 = ia0; sa0 = s; ia0 = j; }
                else if (s > sa1) { sa3 = sa2; ia3 = ia2; sa2 = sa1; ia2 = ia1; sa1 = s; ia1 = j; }
                else if (s > sa2) { sa3 = sa2; ia3 = ia2; sa2 = s; ia2 = j; }
                else if (s > sa3) { sa3 = s; ia3 = j; }
            }
            {
                const float s = sj[3]; const int j = jb + 3;
                if (s > sb0)      { sb3 = sb2; ib3 = ib2; sb2 = sb1; ib2 = ib1; sb1 = sb0; ib1 = ib0; sb0 = s; ib0 = j; }
                else if (s > sb1) { sb3 = sb2; ib3 = ib2; sb2 = sb1; ib2 = ib1; sb1 = s; ib1 = j; }
                else if (s > sb2) { sb3 = sb2; ib3 = ib2; sb2 = s; ib2 = j; }
                else if (s > sb3) { sb3 = s; ib3 = j; }
            }
        }
        // stable 4-way merge: on equal scores pick the lower index (global
        // stability, matching the single-chain insertion exactly).
        int i0, i1, i2, i3;
        {
            int im[4];
#pragma unroll
            for (int t = 0; t < 4; ++t) {
                const bool takeA = (sa0 > sb0) || ((sa0 == sb0) && (ia0 < ib0));
                im[t] = takeA ? ia0 : ib0;
                if (takeA) {
                    sa0 = sa1; ia0 = ia1; sa1 = sa2; ia1 = ia2;
                    sa2 = sa3; ia2 = ia3; sa3 = -INFINITY; ia3 = 1 << 30;
                } else {
                    sb0 = sb1; ib0 = ib1; sb1 = sb2; ib1 = ib2;
                    sb2 = sb3; ib2 = ib3; sb3 = -INFINITY; ib3 = 1 << 30;
                }
            }
            i0 = im[0]; i1 = im[1]; i2 = im[2]; i3 = im[3];
        }

        // ---- fused: u = ba + Wtop^T h AND v = Wlow^T h (one splat per e) ----
        u64 uu[10], vv[10];
        {
            const ulonglong2* bp = reinterpret_cast<const ulonglong2*>(sW + E_BA);
#pragma unroll
            for (int q = 0; q < 5; ++q) {
                ulonglong2 t = bp[q];
                uu[2 * q] = t.x; uu[2 * q + 1] = t.y;
                vv[2 * q] = 0ull; vv[2 * q + 1] = 0ull;
            }
#pragma unroll
            for (int e = 0; e < HD; ++e) {
                u64 f = splat2(h[e]);
                const ulonglong2* wt = reinterpret_cast<const ulonglong2*>(sW + E_WA + e * HD);
                const ulonglong2* wl = reinterpret_cast<const ulonglong2*>(sW + E_WA + (HD + e) * HD);
#pragma unroll
                for (int q = 0; q < 5; ++q) {
                    ulonglong2 a = wt[q], c = wl[q];
                    uu[2 * q]     = fma2v(f, a.x, uu[2 * q]);
                    uu[2 * q + 1] = fma2v(f, a.y, uu[2 * q + 1]);
                    vv[2 * q]     = fma2v(f, c.x, vv[2 * q]);
                    vv[2 * q + 1] = fma2v(f, c.y, vv[2 * q + 1]);
                }
            }
        }
        __syncthreads();  // all KNN readers of sh (h) are done; sh can be reused for v

        // ---- sh[tid] = v; uwf = u - v (20 scalars) ----
        float uwf[HD];
        {
            ulonglong2* vp = reinterpret_cast<ulonglong2*>(&sh[tid][0]);
#pragma unroll
            for (int q = 0; q < 5; ++q) {
                ulonglong2 t; t.x = vv[2 * q]; t.y = vv[2 * q + 1];
                vp[q] = t;
            }
#pragma unroll
            for (int q = 0; q < 10; ++q) {
                float ua, ub, va, vb;
                up2(uu[q], ua, ub); up2(vv[q], va, vb);
                uwf[2 * q] = ua - va;
                uwf[2 * q + 1] = ub - vb;
            }
        }
        __syncthreads();  // v of all threads visible in sh

        // ---- EdgeConv: sum_k elu(elu(uwf + v_j) @ Wb + bb) * valid_j ----
        float acc[HD];
#pragma unroll
        for (int d = 0; d < HD; ++d) acc[d] = 0.f;

        auto do_pass = [&](int j0, int j1) {
            const ulonglong2* vp0 = reinterpret_cast<const ulonglong2*>(&sh[j0][0]);
            const ulonglong2* vp1 = reinterpret_cast<const ulonglong2*>(&sh[j1][0]);
            u64 n0[10], n1[10];
            {
                const ulonglong2* bp = reinterpret_cast<const ulonglong2*>(sW + E_BB);
#pragma unroll
                for (int q = 0; q < 5; ++q) {
                    ulonglong2 t = bp[q];
                    n0[2 * q] = t.x; n0[2 * q + 1] = t.y;
                    n1[2 * q] = t.x; n1[2 * q + 1] = t.y;
                }
            }
            // e-loop grouped by quads: one LDS.128 per neighbor per 4 features.
            // FMA accumulation order (e ascending) identical to scalar version.
#pragma unroll 1
            for (int g = 0; g < 5; ++g) {
                ulonglong2 t0 = vp0[g];
                ulonglong2 t1 = vp1[g];
                float a00, a01, a02, a03, a10, a11, a12, a13;
                up2(t0.x, a00, a01); up2(t0.y, a02, a03);
                up2(t1.x, a10, a11); up2(t1.y, a12, a13);
                float q0[4] = {a00, a01, a02, a03};
                float q1[4] = {a10, a11, a12, a13};
#pragma unroll
                for (int k = 0; k < 4; ++k) {
                    const int e = 4 * g + k;
                    const float uwe = uwf[e];
                    u64 f0 = splat2(eluf(uwe + q0[k]));
                    u64 f1 = splat2(eluf(uwe + q1[k]));
                    const ulonglong2* wp =
                        reinterpret_cast<const ulonglong2*>(sW + E_WB + e * HD);
#pragma unroll
                    for (int q = 0; q < 5; ++q) {
                        ulonglong2 w = wp[q];
                        n0[2 * q]     = fma2v(f0, w.x, n0[2 * q]);
                        n0[2 * q + 1] = fma2v(f0, w.y, n0[2 * q + 1]);
                        n1[2 * q]     = fma2v(f1, w.x, n1[2 * q]);
                        n1[2 * q + 1] = fma2v(f1, w.y, n1[2 * q + 1]);
                    }
                }
            }
            // elu + masked accumulate (neighbor order preserved: j0 then j1)
            const float fj0 = sval[j0];
            const float fj1 = sval[j1];
#pragma unroll
            for (int q = 0; q < 10; ++q) {
                float va, vb;
                up2(n0[q], va, vb);
                acc[2 * q]     = fmaf(eluf(va), fj0, acc[2 * q]);
                acc[2 * q + 1] = fmaf(eluf(vb), fj0, acc[2 * q + 1]);
                up2(n1[q], va, vb);
                acc[2 * q]     = fmaf(eluf(va), fj1, acc[2 * q]);
                acc[2 * q + 1] = fmaf(eluf(vb), fj1, acc[2 * q + 1]);
            }
        };
        do_pass(i0, i1);
        do_pass(i2, i3);

        const float mv = myvalid ? 1.f : 0.f;
        __syncthreads();   // everyone done reading sh (v) in do_pass
        // reuse sh for edgeconv output
#pragma unroll
        for (int q = 0; q < 5; ++q)
            reinterpret_cast<float4*>(&sh[tid][0])[q] =
                make_float4(acc[4 * q] * mv, acc[4 * q + 1] * mv,
                            acc[4 * q + 2] * mv, acc[4 * q + 3] * mv);
        sc[tid] = myvalid ? min(tid, i0) : PTS;
        __syncthreads();

        // ---- pool: thread tid owns cluster slot tid (sc loaded as int4) ----
        float pm[HD];
#pragma unroll
        for (int d = 0; d < HD; ++d) pm[d] = -INFINITY;
        int pcnt = 0;
#pragma unroll 1
        for (int jb = 0; jb < PTS; jb += 4) {
            const int4 cc = *reinterpret_cast<const int4*>(&sc[jb]);
#pragma unroll
            for (int k = 0; k < 4; ++k) {
                const int cj = (k == 0) ? cc.x : (k == 1) ? cc.y
                             : (k == 2) ? cc.z : cc.w;
                if (cj == tid) {
                    ++pcnt;
                    const int j = jb + k;
#pragma unroll
                    for (int q = 0; q < 5; ++q) {
                        float4 v = *reinterpret_cast<const float4*>(&sh[j][4 * q]);
                        pm[4 * q + 0] = fmaxf(pm[4 * q + 0], v.x);
                        pm[4 * q + 1] = fmaxf(pm[4 * q + 1], v.y);
                        pm[4 * q + 2] = fmaxf(pm[4 * q + 2], v.z);
                        pm[4 * q + 3] = fmaxf(pm[4 * q + 3], v.w);
                    }
                }
            }
        }
        myvalid = (pcnt > 0);
        sval[tid] = myvalid ? 1.f : 0.f;
#pragma unroll
        for (int d = 0; d < HD; ++d) h[d] = myvalid ? pm[d] : 0.f;
    }

    // ---- global max over valid points ----
    __syncthreads();   // pool readers of sh are done
#pragma unroll
    for (int d = 0; d < HD; ++d) sh[tid][d] = myvalid ? h[d] : -INFINITY;
    __syncthreads();
    if (tid < HD) {
        float g = -INFINITY;
#pragma unroll 4
        for (int j = 0; j < PTS; ++j) g = fmaxf(g, sh[j][tid]);
        sg[tid] = g;
    }
    __syncthreads();

    // ---- output MLP (weights straight from L2; e-loops fully unrolled so
    // all 20 LDGs batch ahead of the serial FMA chain; per-accumulator
    // order unchanged -> bit-identical) ----
    if (tid < HD) {
        float a = bo0[tid];
#pragma unroll
        for (int e = 0; e < HD; ++e) a = fmaf(sg[e], Wo0[e * HD + tid], a);
        sg2[tid] = eluf(a);
    }
    __syncthreads();
    if (tid < HD) {
        float a = bo1[tid];
#pragma unroll
        for (int e = 0; e < HD; ++e) a = fmaf(sg2[e], Wo1[e * HD + tid], a);
        sg[tid] = eluf(a);
    }
    __syncthreads();
    if (tid < 10) {
        float a = bo2[tid];
#pragma unroll
        for (int e = 0; e < HD; ++e) a = fmaf(sg[e], Wo2[e * 10 + tid], a);
        slog[tid] = a;
    }
    __syncthreads();
    if (tid == 0) {
        float mx = slog[0];
#pragma unroll
        for (int i = 1; i < 10; ++i) mx = fmaxf(mx, slog[i]);
        float ssum = 0.f;
#pragma unroll
        for (int i = 0; i < 10; ++i) ssum += expf(slog[i] - mx);
        slse = mx + logf(ssum);
    }
    __syncthreads();
    if (tid < 10) out[b * 10 + tid] = slog[tid] - slse;
}

extern "C" void kernel_launch(void* const* d_in, const int* in_sizes, int n_in,
                              void* d_out, int out_size) {
    const float* x = (const float*)d_in[0];
    const int B = in_sizes[0] / (PTS * 3);
    net_kernel<<<B, PTS>>>(
        x,
        (const float*)d_in[1],  (const float*)d_in[2],
        (const float*)d_in[3],  (const float*)d_in[4],
        (const float*)d_in[5],  (const float*)d_in[6],
        (const float*)d_in[7],  (const float*)d_in[8],
        (const float*)d_in[9],  (const float*)d_in[10],
        (const float*)d_in[11], (const float*)d_in[12],
        (const float*)d_in[13], (const float*)d_in[14],
        (const float*)d_in[15], (const float*)d_in[16],
        (const float*)d_in[17], (const float*)d_in[18],
        (const float*)d_in[19], (const float*)d_in[20],
        (float*)d_out);
}